// round 2
// baseline (speedup 1.0000x reference)
#include <cuda_runtime.h>

#define Bn 4
#define Cn 128
#define Hn 128
#define Wn 128
#define On 256
#define HWn (Hn*Wn)
#define OT 64

// Scratch (allocation-free rule: __device__ globals)
__device__ float g_mid[Bn*Cn*HWn];      // depthwise output, 33.5 MB
__device__ float g_dy[Bn*9*HWn];
__device__ float g_dx[Bn*9*HWn];
__device__ float g_mask[Bn*9*HWn];
__device__ float g_woffT[Cn*9*28];      // w_off transposed to [c][j][o], o padded to 28

// ---------------------------------------------------------------------------
// K0: transpose offset-conv weights [o][c][j] -> [c][j][o] (padded) so K1 can
// stage them into smem with coalesced loads.
// ---------------------------------------------------------------------------
__global__ void k0_transpose(const float* __restrict__ w_off) {
    int idx = blockIdx.x * 256 + threadIdx.x;
    if (idx >= Cn*9*28) return;
    int c = idx / (9*28);
    int r = idx % (9*28);
    int j = r / 28, o = r % 28;
    g_woffT[idx] = (o < 27) ? w_off[(o*Cn + c)*9 + j] : 0.f;
}

// ---------------------------------------------------------------------------
// K1: offset/mask conv. Block = (h, b), 128 threads over w.
// Per channel: stage 3 input rows + 9x27 weights in smem, 243 FFMA/thread.
// Emits dy, dx, sigmoid(mask) per (b, k, h, w).
// ---------------------------------------------------------------------------
__global__ __launch_bounds__(Wn) void k1_offset(const float* __restrict__ x,
                                                const float* __restrict__ b_off) {
    int h = blockIdx.x, b = blockIdx.y, w = threadIdx.x;
    __shared__ float sx[3][Wn+2];
    __shared__ float sw[9*28];

    if (w < 3) { sx[w][0] = 0.f; sx[w][Wn+1] = 0.f; }

    float acc[27];
    #pragma unroll
    for (int o = 0; o < 27; o++) acc[o] = b_off[o];

    const float* xb = x + (size_t)b*Cn*HWn;

    for (int c = 0; c < Cn; c++) {
        __syncthreads();
        #pragma unroll
        for (int r = 0; r < 3; r++) {
            int row = h - 1 + r;
            sx[r][w+1] = (row >= 0 && row < Hn) ? xb[c*HWn + row*Wn + w] : 0.f;
        }
        const float* wc = g_woffT + c*9*28;
        for (int t = w; t < 9*28; t += Wn) sw[t] = wc[t];
        __syncthreads();

        float xv[9];
        #pragma unroll
        for (int j = 0; j < 9; j++) xv[j] = sx[j/3][w + (j%3)];
        #pragma unroll
        for (int j = 0; j < 9; j++) {
            #pragma unroll
            for (int o = 0; o < 27; o++)
                acc[o] = fmaf(xv[j], sw[j*28 + o], acc[o]);
        }
    }

    int base = h*Wn + w;
    #pragma unroll
    for (int k = 0; k < 9; k++) {
        g_dy[(b*9+k)*HWn + base] = acc[2*k];
        g_dx[(b*9+k)*HWn + base] = acc[2*k+1];
        g_mask[(b*9+k)*HWn + base] = 1.f / (1.f + expf(-acc[18+k]));
    }
}

// ---------------------------------------------------------------------------
// K2: bilinear gather * mask, fused with depthwise 3x3. Block = (h, b),
// 128 threads over w. Tap indices/weights computed ONCE per pixel (registers),
// reused across all 128 channels. Writes mid[b][c][h][w].
// ---------------------------------------------------------------------------
__global__ __launch_bounds__(Wn) void k2_sample(const float* __restrict__ x,
                                                const float* __restrict__ w_dw,
                                                const float* __restrict__ b_dw) {
    int h = blockIdx.x, b = blockIdx.y, w = threadIdx.x;
    __shared__ float swdw[Cn*9];
    __shared__ float sbdw[Cn];
    for (int t = threadIdx.x; t < Cn*9; t += Wn) swdw[t] = w_dw[t];
    if (threadIdx.x < Cn) sbdw[threadIdx.x] = b_dw[threadIdx.x];

    int   idx4[9][4];
    float wt4[9][4];
    int base = h*Wn + w;

    #pragma unroll
    for (int k = 0; k < 9; k++) {
        int off = (b*9+k)*HWn + base;
        float dyv = g_dy[off], dxv = g_dx[off], m = g_mask[off];
        float py = (float)(h + k/3 - 1) + dyv;
        float px = (float)(w + k%3 - 1) + dxv;
        float y0f = floorf(py), x0f = floorf(px);
        float wy = py - y0f, wx = px - x0f;
        int y0 = (int)y0f, x0 = (int)x0f;
        #pragma unroll
        for (int corner = 0; corner < 4; corner++) {
            int yy = y0 + (corner >> 1);
            int xx = x0 + (corner & 1);
            float bw = ((corner >> 1) ? wy : 1.f - wy) *
                       ((corner & 1)  ? wx : 1.f - wx);
            bool valid = (yy >= 0) && (yy < Hn) && (xx >= 0) && (xx < Wn);
            int yi = min(max(yy, 0), Hn-1);
            int xi = min(max(xx, 0), Wn-1);
            idx4[k][corner] = yi*Wn + xi;
            wt4[k][corner]  = valid ? bw * m : 0.f;   // mask & validity folded in
        }
    }
    __syncthreads();

    const float* xb = x + (size_t)b*Cn*HWn;
    float* midb = g_mid + (size_t)b*Cn*HWn + base;

    for (int c = 0; c < Cn; c++) {
        const float* xc = xb + c*HWn;
        float acc = sbdw[c];
        #pragma unroll
        for (int k = 0; k < 9; k++) {
            float v = wt4[k][0]*xc[idx4[k][0]]
                    + wt4[k][1]*xc[idx4[k][1]]
                    + wt4[k][2]*xc[idx4[k][2]]
                    + wt4[k][3]*xc[idx4[k][3]];
            acc = fmaf(swdw[c*9+k], v, acc);
        }
        midb[c*HWn] = acc;
    }
}

// ---------------------------------------------------------------------------
// K3: pointwise 1x1 (GEMM M=256, K=128, N=B*HW). Block: 128 p-lanes x 64 o.
// 64 fp32 accumulators per thread; weights smem-broadcast; mid loads coalesced.
// 64 FFMA per global load.
// ---------------------------------------------------------------------------
__global__ __launch_bounds__(128) void k3_pointwise(const float* __restrict__ w_pw,
                                                    const float* __restrict__ b_pw,
                                                    float* __restrict__ out) {
    __shared__ float swp[Cn][OT+4];   // [c][o_local], row stride 68 (16B aligned)
    int tid = threadIdx.x;
    int o0 = blockIdx.y * OT;
    for (int i = tid; i < OT*Cn; i += 128) {
        int ol = i / Cn, c = i % Cn;
        swp[c][ol] = w_pw[(o0 + ol)*Cn + c];
    }
    __syncthreads();

    int b = blockIdx.z;
    int p = blockIdx.x * 128 + tid;
    const float* midp = g_mid + (size_t)b*Cn*HWn + p;

    float acc[OT];
    #pragma unroll
    for (int i = 0; i < OT; i++) acc[i] = 0.f;

    for (int c = 0; c < Cn; c++) {
        float mv = midp[c*HWn];
        #pragma unroll
        for (int i = 0; i < OT; i++)
            acc[i] = fmaf(mv, swp[c][i], acc[i]);
    }

    float* outp = out + (size_t)b*On*HWn + p;
    #pragma unroll
    for (int i = 0; i < OT; i++)
        outp[(o0 + i)*HWn] = acc[i] + b_pw[o0 + i];
}

// ---------------------------------------------------------------------------
extern "C" void kernel_launch(void* const* d_in, const int* in_sizes, int n_in,
                              void* d_out, int out_size) {
    const float* x     = (const float*)d_in[0];
    const float* w_off = (const float*)d_in[1];
    const float* b_off = (const float*)d_in[2];
    const float* w_dw  = (const float*)d_in[3];
    const float* b_dw  = (const float*)d_in[4];
    const float* w_pw  = (const float*)d_in[5];
    const float* b_pw  = (const float*)d_in[6];
    float* out = (float*)d_out;

    k0_transpose<<<(Cn*9*28 + 255)/256, 256>>>(w_off);
    k1_offset   <<<dim3(Hn, Bn), Wn>>>(x, b_off);
    k2_sample   <<<dim3(Hn, Bn), Wn>>>(x, w_dw, b_dw);
    k3_pointwise<<<dim3(HWn/128, On/OT, Bn), 128>>>(w_pw, b_pw, out);
}

// round 4
// speedup vs baseline: 1.2818x; 1.2818x over previous
#include <cuda_runtime.h>
#include <cstdint>

#define Bn 4
#define Cn 128
#define Hn 128
#define Wn 128
#define On 256
#define HWn (Hn*Wn)

// Scratch (allocation-free rule: __device__ globals)
__device__ float g_mid[Bn*Cn*HWn];      // depthwise output, 33.5 MB
__device__ float g_dy[Bn*9*HWn];
__device__ float g_dx[Bn*9*HWn];
__device__ float g_mask[Bn*9*HWn];
__device__ float g_woffT[Cn*9*28];      // w_off transposed to [c][j][o], o padded to 28

__device__ __forceinline__ uint32_t f2tf32(float f) {
    uint32_t u;
    asm("cvt.rna.tf32.f32 %0, %1;" : "=r"(u) : "f"(f));
    return u;
}

__device__ __forceinline__ void mma_tf32(float& d0, float& d1, float& d2, float& d3,
                                         uint32_t a0, uint32_t a1, uint32_t a2, uint32_t a3,
                                         uint32_t b0, uint32_t b1) {
    asm volatile(
        "mma.sync.aligned.m16n8k8.row.col.f32.tf32.tf32.f32 "
        "{%0,%1,%2,%3}, {%4,%5,%6,%7}, {%8,%9}, {%0,%1,%2,%3};"
        : "+f"(d0), "+f"(d1), "+f"(d2), "+f"(d3)
        : "r"(a0), "r"(a1), "r"(a2), "r"(a3), "r"(b0), "r"(b1));
}

// ---------------------------------------------------------------------------
// K0: transpose offset-conv weights [o][c][j] -> [c][j][o] (padded).
// ---------------------------------------------------------------------------
__global__ void k0_transpose(const float* __restrict__ w_off) {
    int idx = blockIdx.x * 256 + threadIdx.x;
    if (idx >= Cn*9*28) return;
    int c = idx / (9*28);
    int r = idx % (9*28);
    int j = r / 28, o = r % 28;
    g_woffT[idx] = (o < 27) ? w_off[(o*Cn + c)*9 + j] : 0.f;
}

// ---------------------------------------------------------------------------
// K1: offset/mask conv. Block = (h, b), 128 threads over w.
// ---------------------------------------------------------------------------
__global__ __launch_bounds__(Wn) void k1_offset(const float* __restrict__ x,
                                                const float* __restrict__ b_off) {
    int h = blockIdx.x, b = blockIdx.y, w = threadIdx.x;
    __shared__ float sx[3][Wn+2];
    __shared__ float sw[9*28];

    if (w < 3) { sx[w][0] = 0.f; sx[w][Wn+1] = 0.f; }

    float acc[27];
    #pragma unroll
    for (int o = 0; o < 27; o++) acc[o] = b_off[o];

    const float* xb = x + (size_t)b*Cn*HWn;

    for (int c = 0; c < Cn; c++) {
        __syncthreads();
        #pragma unroll
        for (int r = 0; r < 3; r++) {
            int row = h - 1 + r;
            sx[r][w+1] = (row >= 0 && row < Hn) ? xb[c*HWn + row*Wn + w] : 0.f;
        }
        const float* wc = g_woffT + c*9*28;
        for (int t = w; t < 9*28; t += Wn) sw[t] = wc[t];
        __syncthreads();

        float xv[9];
        #pragma unroll
        for (int j = 0; j < 9; j++) xv[j] = sx[j/3][w + (j%3)];
        #pragma unroll
        for (int j = 0; j < 9; j++) {
            #pragma unroll
            for (int o = 0; o < 27; o++)
                acc[o] = fmaf(xv[j], sw[j*28 + o], acc[o]);
        }
    }

    int base = h*Wn + w;
    #pragma unroll
    for (int k = 0; k < 9; k++) {
        g_dy[(b*9+k)*HWn + base] = acc[2*k];
        g_dx[(b*9+k)*HWn + base] = acc[2*k+1];
        g_mask[(b*9+k)*HWn + base] = 1.f / (1.f + expf(-acc[18+k]));
    }
}

// ---------------------------------------------------------------------------
// K2: bilinear gather * mask, fused with depthwise 3x3.
// ---------------------------------------------------------------------------
__global__ __launch_bounds__(Wn) void k2_sample(const float* __restrict__ x,
                                                const float* __restrict__ w_dw,
                                                const float* __restrict__ b_dw) {
    int h = blockIdx.x, b = blockIdx.y, w = threadIdx.x;
    __shared__ float swdw[Cn*9];
    __shared__ float sbdw[Cn];
    for (int t = threadIdx.x; t < Cn*9; t += Wn) swdw[t] = w_dw[t];
    if (threadIdx.x < Cn) sbdw[threadIdx.x] = b_dw[threadIdx.x];

    int   idx4[9][4];
    float wt4[9][4];
    int base = h*Wn + w;

    #pragma unroll
    for (int k = 0; k < 9; k++) {
        int off = (b*9+k)*HWn + base;
        float dyv = g_dy[off], dxv = g_dx[off], m = g_mask[off];
        float py = (float)(h + k/3 - 1) + dyv;
        float px = (float)(w + k%3 - 1) + dxv;
        float y0f = floorf(py), x0f = floorf(px);
        float wy = py - y0f, wx = px - x0f;
        int y0 = (int)y0f, x0 = (int)x0f;
        #pragma unroll
        for (int corner = 0; corner < 4; corner++) {
            int yy = y0 + (corner >> 1);
            int xx = x0 + (corner & 1);
            float bw = ((corner >> 1) ? wy : 1.f - wy) *
                       ((corner & 1)  ? wx : 1.f - wx);
            bool valid = (yy >= 0) && (yy < Hn) && (xx >= 0) && (xx < Wn);
            int yi = min(max(yy, 0), Hn-1);
            int xi = min(max(xx, 0), Wn-1);
            idx4[k][corner] = yi*Wn + xi;
            wt4[k][corner]  = valid ? bw * m : 0.f;
        }
    }
    __syncthreads();

    const float* xb = x + (size_t)b*Cn*HWn;
    float* midb = g_mid + (size_t)b*Cn*HWn + base;

    for (int c = 0; c < Cn; c++) {
        const float* xc = xb + c*HWn;
        float acc = sbdw[c];
        #pragma unroll
        for (int k = 0; k < 9; k++) {
            float v = wt4[k][0]*xc[idx4[k][0]]
                    + wt4[k][1]*xc[idx4[k][1]]
                    + wt4[k][2]*xc[idx4[k][2]]
                    + wt4[k][3]*xc[idx4[k][3]];
            acc = fmaf(swdw[c*9+k], v, acc);
        }
        midb[c*HWn] = acc;
    }
}

// ---------------------------------------------------------------------------
// K3: pointwise 1x1 as tf32 mma.sync GEMM.
// CTA: D[128 o][128 px] = W[128 o][128 c] * mid[128 c][128 px]
// 256 threads = 8 warps (2 M x 4 N), warp tile 64x32, m16n8k8.
// smem: A[o][c] pitch 132 (A-frag banks = lane), B[c][p] pitch 136 (tig*8+g).
// ---------------------------------------------------------------------------
#define PA 132
#define PB 136
#define K3_SMEM ((128*PA + 128*PB) * 4)

__global__ __launch_bounds__(256) void k3_mma(const float* __restrict__ w_pw,
                                              const float* __restrict__ b_pw,
                                              float* __restrict__ out) {
    extern __shared__ uint32_t smem[];
    uint32_t* sA = smem;             // 128 x PA
    uint32_t* sB = smem + 128*PA;    // 128 x PB

    int tid = threadIdx.x;
    int wid = tid >> 5, lid = tid & 31;
    int g = lid >> 2, tig = lid & 3;
    int wm = wid >> 2, wn = wid & 3;         // 2 x 4 warp grid

    int o0  = blockIdx.y * 128;
    int p0  = blockIdx.x * 128;
    int b   = p0 / HWn;
    int hw0 = p0 % HWn;

    // ---- stage A (weights -> tf32) ----
    #pragma unroll
    for (int it = 0; it < 16; it++) {
        int i = it*256 + tid;
        int m = i >> 5, q = i & 31;
        float4 v = *(const float4*)(w_pw + (size_t)(o0 + m)*Cn + q*4);
        uint4 u = { f2tf32(v.x), f2tf32(v.y), f2tf32(v.z), f2tf32(v.w) };
        *(uint4*)(sA + m*PA + q*4) = u;
    }
    // ---- stage B (mid tile -> tf32) ----
    const float* midb = g_mid + (size_t)b*Cn*HWn + hw0;
    #pragma unroll
    for (int it = 0; it < 16; it++) {
        int i = it*256 + tid;
        int c = i >> 5, v = i & 31;
        float4 val = *(const float4*)(midb + (size_t)c*HWn + v*4);
        uint4 u = { f2tf32(val.x), f2tf32(val.y), f2tf32(val.z), f2tf32(val.w) };
        *(uint4*)(sB + c*PB + v*4) = u;
    }
    __syncthreads();

    float acc[4][4][4];
    #pragma unroll
    for (int mi = 0; mi < 4; mi++)
        #pragma unroll
        for (int ni = 0; ni < 4; ni++)
            #pragma unroll
            for (int j = 0; j < 4; j++) acc[mi][ni][j] = 0.f;

    const uint32_t* sAr = sA + (wm*64 + g)*PA;    // row g of this warp's M block
    const uint32_t* sBr = sB + wn*32 + g;         // col g of this warp's N block

    #pragma unroll
    for (int ks = 0; ks < 16; ks++) {
        int c0 = ks*8;
        uint32_t a[4][4], bf[4][2];
        #pragma unroll
        for (int mi = 0; mi < 4; mi++) {
            const uint32_t* p = sAr + mi*16*PA + c0 + tig;
            a[mi][0] = p[0];
            a[mi][1] = p[8*PA];
            a[mi][2] = p[4];
            a[mi][3] = p[8*PA + 4];
        }
        #pragma unroll
        for (int ni = 0; ni < 4; ni++) {
            const uint32_t* p = sBr + (c0 + tig)*PB + ni*8;
            bf[ni][0] = p[0];
            bf[ni][1] = p[4*PB];
        }
        #pragma unroll
        for (int mi = 0; mi < 4; mi++)
            #pragma unroll
            for (int ni = 0; ni < 4; ni++)
                mma_tf32(acc[mi][ni][0], acc[mi][ni][1], acc[mi][ni][2], acc[mi][ni][3],
                         a[mi][0], a[mi][1], a[mi][2], a[mi][3],
                         bf[ni][0], bf[ni][1]);
    }

    // ---- epilogue: direct gmem stores (float2 per lane per row) ----
    float* outb = out + (size_t)b*On*HWn + hw0 + wn*32;
    #pragma unroll
    for (int mi = 0; mi < 4; mi++) {
        int row = o0 + wm*64 + mi*16 + g;
        float bias0 = b_pw[row];
        float bias1 = b_pw[row + 8];
        float* r0 = outb + (size_t)row*HWn;
        float* r1 = outb + (size_t)(row + 8)*HWn;
        #pragma unroll
        for (int ni = 0; ni < 4; ni++) {
            int col = ni*8 + 2*tig;
            *(float2*)(r0 + col) = make_float2(acc[mi][ni][0] + bias0,
                                               acc[mi][ni][1] + bias0);
            *(float2*)(r1 + col) = make_float2(acc[mi][ni][2] + bias1,
                                               acc[mi][ni][3] + bias1);
        }
    }
}

// ---------------------------------------------------------------------------
extern "C" void kernel_launch(void* const* d_in, const int* in_sizes, int n_in,
                              void* d_out, int out_size) {
    const float* x     = (const float*)d_in[0];
    const float* w_off = (const float*)d_in[1];
    const float* b_off = (const float*)d_in[2];
    const float* w_dw  = (const float*)d_in[3];
    const float* b_dw  = (const float*)d_in[4];
    const float* w_pw  = (const float*)d_in[5];
    const float* b_pw  = (const float*)d_in[6];
    float* out = (float*)d_out;

    cudaFuncSetAttribute(k3_mma, cudaFuncAttributeMaxDynamicSharedMemorySize, K3_SMEM);

    k0_transpose<<<(Cn*9*28 + 255)/256, 256>>>(w_off);
    k1_offset   <<<dim3(Hn, Bn), Wn>>>(x, b_off);
    k2_sample   <<<dim3(Hn, Bn), Wn>>>(x, w_dw, b_dw);
    k3_mma      <<<dim3(Bn*HWn/128, On/128), 256, K3_SMEM>>>(w_pw, b_pw, out);
}

// round 6
// speedup vs baseline: 1.8957x; 1.4790x over previous
#include <cuda_runtime.h>
#include <cstdint>

#define Bn 4
#define Cn 128
#define Hn 128
#define Wn 128
#define On 256
#define HWn (Hn*Wn)

// Scratch (allocation-free rule: __device__ globals)
__device__ float g_mid[Bn*Cn*HWn];      // depthwise output, 33.5 MB
__device__ float g_om[Bn*32*HWn];       // raw offset-conv output, 32 ch (27 used)
__device__ float g_wk1h[32*9*128];      // offset-conv weights tf32-hi [o][tap][c]
__device__ float g_wk1l[32*9*128];      // offset-conv weights tf32-lo

__device__ __forceinline__ uint32_t f2tf32(float f) {
    uint32_t u;
    asm("cvt.rna.tf32.f32 %0, %1;" : "=r"(u) : "f"(f));
    return u;
}

__device__ __forceinline__ void mma_tf32(float* d,
                                         uint32_t a0, uint32_t a1, uint32_t a2, uint32_t a3,
                                         uint32_t b0, uint32_t b1) {
    asm volatile(
        "mma.sync.aligned.m16n8k8.row.col.f32.tf32.tf32.f32 "
        "{%0,%1,%2,%3}, {%4,%5,%6,%7}, {%8,%9}, {%0,%1,%2,%3};"
        : "+f"(d[0]), "+f"(d[1]), "+f"(d[2]), "+f"(d[3])
        : "r"(a0), "r"(a1), "r"(a2), "r"(a3), "r"(b0), "r"(b1));
}

// ---------------------------------------------------------------------------
// K0: build tf32 hi/lo split of offset-conv weights as [o pad32][tap][c].
// ---------------------------------------------------------------------------
__global__ void k0_wk1(const float* __restrict__ w_off) {
    int idx = blockIdx.x * 256 + threadIdx.x;
    if (idx >= 32*1152) return;
    int o = idx / 1152, r = idx % 1152;      // r = tap*128 + c
    int tap = r >> 7, c = r & 127;
    float v = (o < 27) ? w_off[(o*Cn + c)*9 + tap] : 0.f;
    uint32_t hi = f2tf32(v);
    g_wk1h[idx] = __uint_as_float(hi);
    g_wk1l[idx] = __uint_as_float(f2tf32(v - __uint_as_float(hi)));
}

// ---------------------------------------------------------------------------
// K1: offset/mask conv as tf32 mma.sync GEMM with 3-MMA precision split.
// CTA = (h-pair, b): D[32 o][256 px] = sum_{tap,c} W[o][tap,c] * x[c][shifted]
// Taps realized as smem pointer offsets into staged x rows (h0-1..h0+2).
// K split into 16 chunks of 8 c; per chunk K = 9 taps x 8 c, k-step = one tap.
// 8 warps: warp w -> px [w*32, w*32+32), all warps cover full M=32.
// ---------------------------------------------------------------------------
#define ROWP 136                 // words per staged row (data cols 4..131)
#define XSTR 552                 // words per channel (4 rows; 552 % 32 == 8)
#define AP   76                  // A pitch (76 % 32 == 12)
#define K1_SMEM ((16*XSTR + 64*AP) * 4)

__global__ __launch_bounds__(256) void k1_mma(const float* __restrict__ x) {
    extern __shared__ float sm[];
    float* sxh = sm;                     // [8 c][4 rows][ROWP]
    float* sxl = sm + 8*XSTR;
    float* sAh = sm + 16*XSTR;           // [32 o][72 k]
    float* sAl = sAh + 32*AP;

    int tid = threadIdx.x, wid = tid >> 5, lid = tid & 31;
    int g = lid >> 2, tig = lid & 3;
    int h0 = blockIdx.x * 2, b = blockIdx.y;

    // zero x smem once (borders must stay 0 across chunks)
    for (int i = tid; i < 16*XSTR; i += 256) sm[i] = 0.f;

    float acc[2][4][4];
    #pragma unroll
    for (int mt = 0; mt < 2; mt++)
        #pragma unroll
        for (int nt = 0; nt < 4; nt++)
            #pragma unroll
            for (int j = 0; j < 4; j++) acc[mt][nt][j] = 0.f;

    int hh  = wid >> 2;                  // output row within pair
    int wc0 = (wid & 3) * 32;            // px column base for this warp

    // staging indices (fixed per thread)
    int s_cl = tid >> 5;                 // 0..7 channel
    int s_r  = (tid >> 3) & 3;           // 0..3 row
    int s_q  = tid & 7;                  // float4 col group

    for (int c0 = 0; c0 < Cn; c0 += 8) {
        __syncthreads();
        // ---- stage x chunk (hi/lo) ----
        {
            int row = h0 - 1 + s_r;
            bool ok = (row >= 0) && (row < Hn);
            const float* xp = x + ((size_t)b*Cn + (c0 + s_cl))*HWn + row*Wn;
            float* dh = sxh + s_cl*XSTR + s_r*ROWP + 4;
            float* dl = sxl + s_cl*XSTR + s_r*ROWP + 4;
            #pragma unroll
            for (int j = 0; j < 4; j++) {
                int col = (s_q + 8*j) * 4;
                float4 v = ok ? *(const float4*)(xp + col) : make_float4(0.f,0.f,0.f,0.f);
                uint4 vh = { f2tf32(v.x), f2tf32(v.y), f2tf32(v.z), f2tf32(v.w) };
                uint4 vl = { f2tf32(v.x - __uint_as_float(vh.x)),
                             f2tf32(v.y - __uint_as_float(vh.y)),
                             f2tf32(v.z - __uint_as_float(vh.z)),
                             f2tf32(v.w - __uint_as_float(vh.w)) };
                *(uint4*)(dh + col) = vh;
                *(uint4*)(dl + col) = vl;
            }
        }
        // ---- stage A chunk ----
        #pragma unroll
        for (int t = 0; t < 9; t++) {
            int i = t*256 + tid;                 // 0..2303
            int o = i / 72, k = i % 72;
            int tap = k >> 3, cl = k & 7;
            int gi = o*1152 + tap*128 + c0 + cl;
            sAh[o*AP + k] = g_wk1h[gi];
            sAl[o*AP + k] = g_wk1l[gi];
        }
        __syncthreads();

        // ---- compute: 9 taps (= k-steps of 8 c) ----
        #pragma unroll
        for (int tap = 0; tap < 9; tap++) {
            const int ty = tap / 3, tx = tap % 3;
            uint32_t ah[2][4], al[2][4];
            #pragma unroll
            for (int mt = 0; mt < 2; mt++) {
                const float* pah = sAh + (mt*16 + g)*AP + tap*8 + tig;
                const float* pal = sAl + (mt*16 + g)*AP + tap*8 + tig;
                ah[mt][0] = __float_as_uint(pah[0]);
                ah[mt][1] = __float_as_uint(pah[8*AP]);
                ah[mt][2] = __float_as_uint(pah[4]);
                ah[mt][3] = __float_as_uint(pah[8*AP + 4]);
                al[mt][0] = __float_as_uint(pal[0]);
                al[mt][1] = __float_as_uint(pal[8*AP]);
                al[mt][2] = __float_as_uint(pal[4]);
                al[mt][3] = __float_as_uint(pal[8*AP + 4]);
            }
            const float* pbh = sxh + tig*XSTR + (hh + ty)*ROWP + 3 + tx + wc0 + g;
            const float* pbl = sxl + tig*XSTR + (hh + ty)*ROWP + 3 + tx + wc0 + g;
            #pragma unroll
            for (int nt = 0; nt < 4; nt++) {
                uint32_t bh0 = __float_as_uint(pbh[nt*8]);
                uint32_t bh1 = __float_as_uint(pbh[nt*8 + 4*XSTR]);
                uint32_t bl0 = __float_as_uint(pbl[nt*8]);
                uint32_t bl1 = __float_as_uint(pbl[nt*8 + 4*XSTR]);
                #pragma unroll
                for (int mt = 0; mt < 2; mt++) {
                    mma_tf32(acc[mt][nt], ah[mt][0], ah[mt][1], ah[mt][2], ah[mt][3], bh0, bh1);
                    mma_tf32(acc[mt][nt], ah[mt][0], ah[mt][1], ah[mt][2], ah[mt][3], bl0, bl1);
                    mma_tf32(acc[mt][nt], al[mt][0], al[mt][1], al[mt][2], al[mt][3], bh0, bh1);
                }
            }
        }
    }

    // ---- epilogue: raw om store (bias/sigmoid applied in k2) ----
    float* omb = g_om + (size_t)b*32*HWn + (h0 + hh)*Wn + wc0;
    #pragma unroll
    for (int mt = 0; mt < 2; mt++) {
        int o0 = mt*16 + g;
        #pragma unroll
        for (int nt = 0; nt < 4; nt++) {
            int col = nt*8 + 2*tig;
            *(float2*)(omb + (size_t)o0*HWn + col) =
                make_float2(acc[mt][nt][0], acc[mt][nt][1]);
            *(float2*)(omb + (size_t)(o0+8)*HWn + col) =
                make_float2(acc[mt][nt][2], acc[mt][nt][3]);
        }
    }
}

// ---------------------------------------------------------------------------
// K2: bilinear gather * mask, fused with depthwise 3x3.
// Now also applies b_off bias + sigmoid (moved out of k1).
// Grid z splits channels: z in {0,1} -> c in [z*64, z*64+64).
// ---------------------------------------------------------------------------
__global__ __launch_bounds__(Wn) void k2_sample(const float* __restrict__ x,
                                                const float* __restrict__ w_dw,
                                                const float* __restrict__ b_dw,
                                                const float* __restrict__ b_off) {
    int h = blockIdx.x, b = blockIdx.y, w = threadIdx.x;
    int cbase = blockIdx.z * 64;
    __shared__ float swdw[Cn*9];
    __shared__ float sbdw[Cn];
    __shared__ float sboff[27];
    for (int t = threadIdx.x; t < Cn*9; t += Wn) swdw[t] = w_dw[t];
    if (threadIdx.x < Cn) sbdw[threadIdx.x] = b_dw[threadIdx.x];
    if (threadIdx.x < 27) sboff[threadIdx.x] = b_off[threadIdx.x];
    __syncthreads();

    int   idx4[9][4];
    float wt4[9][4];
    int base = h*Wn + w;
    const float* omb = g_om + (size_t)b*32*HWn + base;

    #pragma unroll
    for (int k = 0; k < 9; k++) {
        float dyv = omb[(size_t)(2*k)*HWn]   + sboff[2*k];
        float dxv = omb[(size_t)(2*k+1)*HWn] + sboff[2*k+1];
        float mr  = omb[(size_t)(18+k)*HWn]  + sboff[18+k];
        float m = 1.f / (1.f + expf(-mr));
        float py = (float)(h + k/3 - 1) + dyv;
        float px = (float)(w + k%3 - 1) + dxv;
        float y0f = floorf(py), x0f = floorf(px);
        float wy = py - y0f, wx = px - x0f;
        int y0 = (int)y0f, x0 = (int)x0f;
        #pragma unroll
        for (int corner = 0; corner < 4; corner++) {
            int yy = y0 + (corner >> 1);
            int xx = x0 + (corner & 1);
            float bw = ((corner >> 1) ? wy : 1.f - wy) *
                       ((corner & 1)  ? wx : 1.f - wx);
            bool valid = (yy >= 0) && (yy < Hn) && (xx >= 0) && (xx < Wn);
            int yi = min(max(yy, 0), Hn-1);
            int xi = min(max(xx, 0), Wn-1);
            idx4[k][corner] = yi*Wn + xi;
            wt4[k][corner]  = valid ? bw * m : 0.f;
        }
    }

    const float* xb = x + (size_t)b*Cn*HWn;
    float* midb = g_mid + (size_t)b*Cn*HWn + base;

    for (int c = cbase; c < cbase + 64; c++) {
        const float* xc = xb + (size_t)c*HWn;
        float acc = sbdw[c];
        #pragma unroll
        for (int k = 0; k < 9; k++) {
            float v = wt4[k][0]*xc[idx4[k][0]]
                    + wt4[k][1]*xc[idx4[k][1]]
                    + wt4[k][2]*xc[idx4[k][2]]
                    + wt4[k][3]*xc[idx4[k][3]];
            acc = fmaf(swdw[c*9+k], v, acc);
        }
        midb[(size_t)c*HWn] = acc;
    }
}

// ---------------------------------------------------------------------------
// K3: pointwise 1x1 as tf32 mma.sync GEMM (unchanged from R3).
// ---------------------------------------------------------------------------
#define PA 132
#define PB 136
#define K3_SMEM ((128*PA + 128*PB) * 4)

__global__ __launch_bounds__(256) void k3_mma(const float* __restrict__ w_pw,
                                              const float* __restrict__ b_pw,
                                              float* __restrict__ out) {
    extern __shared__ uint32_t smem[];
    uint32_t* sA = smem;             // 128 x PA
    uint32_t* sB = smem + 128*PA;    // 128 x PB

    int tid = threadIdx.x;
    int wid = tid >> 5, lid = tid & 31;
    int g = lid >> 2, tig = lid & 3;
    int wm = wid >> 2, wn = wid & 3;

    int o0  = blockIdx.y * 128;
    int p0  = blockIdx.x * 128;
    int b   = p0 / HWn;
    int hw0 = p0 % HWn;

    #pragma unroll
    for (int it = 0; it < 16; it++) {
        int i = it*256 + tid;
        int m = i >> 5, q = i & 31;
        float4 v = *(const float4*)(w_pw + (size_t)(o0 + m)*Cn + q*4);
        uint4 u = { f2tf32(v.x), f2tf32(v.y), f2tf32(v.z), f2tf32(v.w) };
        *(uint4*)(sA + m*PA + q*4) = u;
    }
    const float* midb = g_mid + (size_t)b*Cn*HWn + hw0;
    #pragma unroll
    for (int it = 0; it < 16; it++) {
        int i = it*256 + tid;
        int c = i >> 5, v = i & 31;
        float4 val = *(const float4*)(midb + (size_t)c*HWn + v*4);
        uint4 u = { f2tf32(val.x), f2tf32(val.y), f2tf32(val.z), f2tf32(val.w) };
        *(uint4*)(sB + c*PB + v*4) = u;
    }
    __syncthreads();

    float acc[4][4][4];
    #pragma unroll
    for (int mi = 0; mi < 4; mi++)
        #pragma unroll
        for (int ni = 0; ni < 4; ni++)
            #pragma unroll
            for (int j = 0; j < 4; j++) acc[mi][ni][j] = 0.f;

    const uint32_t* sAr = sA + (wm*64 + g)*PA;
    const uint32_t* sBr = sB + wn*32 + g;

    #pragma unroll
    for (int ks = 0; ks < 16; ks++) {
        int c0 = ks*8;
        uint32_t a[4][4], bf[4][2];
        #pragma unroll
        for (int mi = 0; mi < 4; mi++) {
            const uint32_t* p = sAr + mi*16*PA + c0 + tig;
            a[mi][0] = p[0];
            a[mi][1] = p[8*PA];
            a[mi][2] = p[4];
            a[mi][3] = p[8*PA + 4];
        }
        #pragma unroll
        for (int ni = 0; ni < 4; ni++) {
            const uint32_t* p = sBr + (c0 + tig)*PB + ni*8;
            bf[ni][0] = p[0];
            bf[ni][1] = p[4*PB];
        }
        #pragma unroll
        for (int mi = 0; mi < 4; mi++)
            #pragma unroll
            for (int ni = 0; ni < 4; ni++)
                mma_tf32(acc[mi][ni], a[mi][0], a[mi][1], a[mi][2], a[mi][3],
                         bf[ni][0], bf[ni][1]);
    }

    float* outb = out + (size_t)b*On*HWn + hw0 + wn*32;
    #pragma unroll
    for (int mi = 0; mi < 4; mi++) {
        int row = o0 + wm*64 + mi*16 + g;
        float bias0 = b_pw[row];
        float bias1 = b_pw[row + 8];
        float* r0 = outb + (size_t)row*HWn;
        float* r1 = outb + (size_t)(row + 8)*HWn;
        #pragma unroll
        for (int ni = 0; ni < 4; ni++) {
            int col = ni*8 + 2*tig;
            *(float2*)(r0 + col) = make_float2(acc[mi][ni][0] + bias0,
                                               acc[mi][ni][1] + bias0);
            *(float2*)(r1 + col) = make_float2(acc[mi][ni][2] + bias1,
                                               acc[mi][ni][3] + bias1);
        }
    }
}

// ---------------------------------------------------------------------------
extern "C" void kernel_launch(void* const* d_in, const int* in_sizes, int n_in,
                              void* d_out, int out_size) {
    const float* x     = (const float*)d_in[0];
    const float* w_off = (const float*)d_in[1];
    const float* b_off = (const float*)d_in[2];
    const float* w_dw  = (const float*)d_in[3];
    const float* b_dw  = (const float*)d_in[4];
    const float* w_pw  = (const float*)d_in[5];
    const float* b_pw  = (const float*)d_in[6];
    float* out = (float*)d_out;

    cudaFuncSetAttribute(k1_mma, cudaFuncAttributeMaxDynamicSharedMemorySize, K1_SMEM);
    cudaFuncSetAttribute(k3_mma, cudaFuncAttributeMaxDynamicSharedMemorySize, K3_SMEM);

    k0_wk1 <<<(32*1152 + 255)/256, 256>>>(w_off);
    k1_mma <<<dim3(Hn/2, Bn), 256, K1_SMEM>>>(x);
    k2_sample<<<dim3(Hn, Bn, 2), Wn>>>(x, w_dw, b_dw, b_off);
    k3_mma <<<dim3(Bn*HWn/128, On/128), 256, K3_SMEM>>>(w_pw, b_pw, out);
}

// round 9
// speedup vs baseline: 2.4808x; 1.3086x over previous
#include <cuda_runtime.h>
#include <cstdint>

#define Bn 4
#define Cn 128
#define Hn 128
#define Wn 128
#define On 256
#define HWn (Hn*Wn)

// Scratch (allocation-free rule: __device__ globals)
__device__ float g_mid[Bn*HWn*Cn];      // depthwise output, [p][c] layout
__device__ float g_xT[Bn*HWn*Cn];       // x transposed to [b][h][w][c]
__device__ float g_om[Bn*32*HWn];       // raw offset-conv output, 32 ch (27 used)
__device__ float g_wk1h[32*9*128];      // offset-conv weights tf32-hi [o][tap][c]
__device__ float g_wk1l[32*9*128];      // offset-conv weights tf32-lo

__device__ __forceinline__ uint32_t f2tf32(float f) {
    uint32_t u;
    asm("cvt.rna.tf32.f32 %0, %1;" : "=r"(u) : "f"(f));
    return u;
}

__device__ __forceinline__ void mma_tf32(float* d,
                                         uint32_t a0, uint32_t a1, uint32_t a2, uint32_t a3,
                                         uint32_t b0, uint32_t b1) {
    asm volatile(
        "mma.sync.aligned.m16n8k8.row.col.f32.tf32.tf32.f32 "
        "{%0,%1,%2,%3}, {%4,%5,%6,%7}, {%8,%9}, {%0,%1,%2,%3};"
        : "+f"(d[0]), "+f"(d[1]), "+f"(d[2]), "+f"(d[3])
        : "r"(a0), "r"(a1), "r"(a2), "r"(a3), "r"(b0), "r"(b1));
}

// ---------------------------------------------------------------------------
// K0: build tf32 hi/lo split of offset-conv weights as [o pad32][tap][c].
// ---------------------------------------------------------------------------
__global__ void k0_wk1(const float* __restrict__ w_off) {
    int idx = blockIdx.x * 256 + threadIdx.x;
    if (idx >= 32*1152) return;
    int o = idx / 1152, r = idx % 1152;      // r = tap*128 + c
    int tap = r >> 7, c = r & 127;
    float v = (o < 27) ? w_off[(o*Cn + c)*9 + tap] : 0.f;
    uint32_t hi = f2tf32(v);
    g_wk1h[idx] = __uint_as_float(hi);
    g_wk1l[idx] = __uint_as_float(f2tf32(v - __uint_as_float(hi)));
}

// ---------------------------------------------------------------------------
// KT: transpose x [b][c][h][w] -> xT [b][hw][c] (channels contiguous).
// 32x32 smem tiles, 256 threads.
// ---------------------------------------------------------------------------
__global__ __launch_bounds__(256) void kT(const float* __restrict__ x) {
    __shared__ float t[32][33];
    int b = blockIdx.z;
    int p0 = blockIdx.x * 32, c0 = blockIdx.y * 32;
    int tx = threadIdx.x & 31, ty = threadIdx.x >> 5;  // 32 x 8
    #pragma unroll
    for (int j = 0; j < 4; j++)
        t[ty + j*8][tx] = x[((size_t)b*Cn + c0 + ty + j*8)*HWn + p0 + tx];
    __syncthreads();
    #pragma unroll
    for (int j = 0; j < 4; j++)
        g_xT[((size_t)b*HWn + p0 + ty + j*8)*128 + c0 + tx] = t[tx][ty + j*8];
}

// ---------------------------------------------------------------------------
// K1: offset/mask conv as tf32 mma.sync GEMM with 3-MMA precision split.
// (unchanged from R5)
// ---------------------------------------------------------------------------
#define ROWP 136
#define XSTR 552
#define AP   76
#define K1_SMEM ((16*XSTR + 64*AP) * 4)

__global__ __launch_bounds__(256) void k1_mma(const float* __restrict__ x) {
    extern __shared__ float sm[];
    float* sxh = sm;
    float* sxl = sm + 8*XSTR;
    float* sAh = sm + 16*XSTR;
    float* sAl = sAh + 32*AP;

    int tid = threadIdx.x, wid = tid >> 5, lid = tid & 31;
    int g = lid >> 2, tig = lid & 3;
    int h0 = blockIdx.x * 2, b = blockIdx.y;

    for (int i = tid; i < 16*XSTR; i += 256) sm[i] = 0.f;

    float acc[2][4][4];
    #pragma unroll
    for (int mt = 0; mt < 2; mt++)
        #pragma unroll
        for (int nt = 0; nt < 4; nt++)
            #pragma unroll
            for (int j = 0; j < 4; j++) acc[mt][nt][j] = 0.f;

    int hh  = wid >> 2;
    int wc0 = (wid & 3) * 32;

    int s_cl = tid >> 5;
    int s_r  = (tid >> 3) & 3;
    int s_q  = tid & 7;

    for (int c0 = 0; c0 < Cn; c0 += 8) {
        __syncthreads();
        {
            int row = h0 - 1 + s_r;
            bool ok = (row >= 0) && (row < Hn);
            const float* xp = x + ((size_t)b*Cn + (c0 + s_cl))*HWn + row*Wn;
            float* dh = sxh + s_cl*XSTR + s_r*ROWP + 4;
            float* dl = sxl + s_cl*XSTR + s_r*ROWP + 4;
            #pragma unroll
            for (int j = 0; j < 4; j++) {
                int col = (s_q + 8*j) * 4;
                float4 v = ok ? *(const float4*)(xp + col) : make_float4(0.f,0.f,0.f,0.f);
                uint4 vh = { f2tf32(v.x), f2tf32(v.y), f2tf32(v.z), f2tf32(v.w) };
                uint4 vl = { f2tf32(v.x - __uint_as_float(vh.x)),
                             f2tf32(v.y - __uint_as_float(vh.y)),
                             f2tf32(v.z - __uint_as_float(vh.z)),
                             f2tf32(v.w - __uint_as_float(vh.w)) };
                *(uint4*)(dh + col) = vh;
                *(uint4*)(dl + col) = vl;
            }
        }
        #pragma unroll
        for (int t = 0; t < 9; t++) {
            int i = t*256 + tid;
            int o = i / 72, k = i % 72;
            int tap = k >> 3, cl = k & 7;
            int gi = o*1152 + tap*128 + c0 + cl;
            sAh[o*AP + k] = g_wk1h[gi];
            sAl[o*AP + k] = g_wk1l[gi];
        }
        __syncthreads();

        #pragma unroll
        for (int tap = 0; tap < 9; tap++) {
            const int ty = tap / 3, tx = tap % 3;
            uint32_t ah[2][4], al[2][4];
            #pragma unroll
            for (int mt = 0; mt < 2; mt++) {
                const float* pah = sAh + (mt*16 + g)*AP + tap*8 + tig;
                const float* pal = sAl + (mt*16 + g)*AP + tap*8 + tig;
                ah[mt][0] = __float_as_uint(pah[0]);
                ah[mt][1] = __float_as_uint(pah[8*AP]);
                ah[mt][2] = __float_as_uint(pah[4]);
                ah[mt][3] = __float_as_uint(pah[8*AP + 4]);
                al[mt][0] = __float_as_uint(pal[0]);
                al[mt][1] = __float_as_uint(pal[8*AP]);
                al[mt][2] = __float_as_uint(pal[4]);
                al[mt][3] = __float_as_uint(pal[8*AP + 4]);
            }
            const float* pbh = sxh + tig*XSTR + (hh + ty)*ROWP + 3 + tx + wc0 + g;
            const float* pbl = sxl + tig*XSTR + (hh + ty)*ROWP + 3 + tx + wc0 + g;
            #pragma unroll
            for (int nt = 0; nt < 4; nt++) {
                uint32_t bh0 = __float_as_uint(pbh[nt*8]);
                uint32_t bh1 = __float_as_uint(pbh[nt*8 + 4*XSTR]);
                uint32_t bl0 = __float_as_uint(pbl[nt*8]);
                uint32_t bl1 = __float_as_uint(pbl[nt*8 + 4*XSTR]);
                #pragma unroll
                for (int mt = 0; mt < 2; mt++) {
                    mma_tf32(acc[mt][nt], ah[mt][0], ah[mt][1], ah[mt][2], ah[mt][3], bh0, bh1);
                    mma_tf32(acc[mt][nt], ah[mt][0], ah[mt][1], ah[mt][2], ah[mt][3], bl0, bl1);
                    mma_tf32(acc[mt][nt], al[mt][0], al[mt][1], al[mt][2], al[mt][3], bh0, bh1);
                }
            }
        }
    }

    float* omb = g_om + (size_t)b*32*HWn + (h0 + hh)*Wn + wc0;
    #pragma unroll
    for (int mt = 0; mt < 2; mt++) {
        int o0 = mt*16 + g;
        #pragma unroll
        for (int nt = 0; nt < 4; nt++) {
            int col = nt*8 + 2*tig;
            *(float2*)(omb + (size_t)o0*HWn + col) =
                make_float2(acc[mt][nt][0], acc[mt][nt][1]);
            *(float2*)(omb + (size_t)(o0+8)*HWn + col) =
                make_float2(acc[mt][nt][2], acc[mt][nt][3]);
        }
    }
}

// ---------------------------------------------------------------------------
// K2: bilinear gather * mask + depthwise 3x3, channel-vectorized.
// CTA = 64 threads (2 warps), tile 16w x 4h; warp handles 16x2 = 32 px.
// Phase 1: lane l computes the 9-tap table (4 idx + 4 wt) for ITS pixel,
//          stores to per-warp smem. Phase 2: warp sweeps 32 px x 9 taps;
//          each corner is ONE coalesced LDG.128 of the 512B channel vector
//          from xT; lane owns channels 4l..4l+3. mid written [p][c].
// ---------------------------------------------------------------------------
__global__ __launch_bounds__(64) void k2_sample(const float* __restrict__ w_dw,
                                                const float* __restrict__ b_dw,
                                                const float* __restrict__ b_off) {
    __shared__ float stap[2*32*72];     // [warp][px][tap][{idx4,wt4}]

    int tid = threadIdx.x, wid = tid >> 5, lid = tid & 31;
    int b  = blockIdx.z;
    int w0 = blockIdx.x * 16;
    int h0 = blockIdx.y * 4 + wid * 2;
    int wl = lid & 15, hl = lid >> 4;

    // per-lane channel weights (c = 4*lid + j)
    float wdw_r[9][4], bdw_r[4];
    #pragma unroll
    for (int j = 0; j < 4; j++) {
        int c = 4*lid + j;
        bdw_r[j] = b_dw[c];
        #pragma unroll
        for (int k = 0; k < 9; k++) wdw_r[k][j] = w_dw[c*9 + k];
    }

    // ---- phase 1: tap table for this lane's pixel ----
    {
        int h = h0 + hl, w = w0 + wl;
        const float* omb = g_om + (size_t)b*32*HWn + h*Wn + w;
        float* myt = stap + wid*32*72 + lid*72;
        #pragma unroll
        for (int k = 0; k < 9; k++) {
            float dyv = omb[(size_t)(2*k)*HWn]   + b_off[2*k];
            float dxv = omb[(size_t)(2*k+1)*HWn] + b_off[2*k+1];
            float mr  = omb[(size_t)(18+k)*HWn]  + b_off[18+k];
            float m = 1.f / (1.f + expf(-mr));
            float py = (float)(h + k/3 - 1) + dyv;
            float px = (float)(w + k%3 - 1) + dxv;
            float y0f = floorf(py), x0f = floorf(px);
            float wy = py - y0f, wx = px - x0f;
            int y0 = (int)y0f, x0 = (int)x0f;
            #pragma unroll
            for (int corner = 0; corner < 4; corner++) {
                int yy = y0 + (corner >> 1);
                int xx = x0 + (corner & 1);
                float bw = ((corner >> 1) ? wy : 1.f - wy) *
                           ((corner & 1)  ? wx : 1.f - wx);
                bool valid = (yy >= 0) && (yy < Hn) && (xx >= 0) && (xx < Wn);
                int yi = min(max(yy, 0), Hn-1);
                int xi = min(max(xx, 0), Wn-1);
                ((uint32_t*)myt)[k*8 + corner] = (uint32_t)((yi*Wn + xi) * 512);
                myt[k*8 + 4 + corner] = valid ? bw * m : 0.f;
            }
        }
    }
    __syncwarp();

    // ---- phase 2: sweep 32 pixels ----
    const char* xTb = (const char*)g_xT + (size_t)b*HWn*512 + lid*16;
    float* midb = g_mid + (size_t)b*HWn*128 + lid*4;
    const float* wt_base = stap + wid*32*72;

    for (int pi = 0; pi < 32; pi++) {
        const float* te = wt_base + pi*72;
        float a0 = bdw_r[0], a1 = bdw_r[1], a2 = bdw_r[2], a3 = bdw_r[3];
        #pragma unroll
        for (int k = 0; k < 9; k++) {
            uint4  I  = *(const uint4*)(te + k*8);        // broadcast LDS
            float4 Wt = *(const float4*)(te + k*8 + 4);
            float4 x0 = *(const float4*)(xTb + I.x);
            float4 x1 = *(const float4*)(xTb + I.y);
            float4 x2 = *(const float4*)(xTb + I.z);
            float4 x3 = *(const float4*)(xTb + I.w);
            float v0 = Wt.x*x0.x + Wt.y*x1.x + Wt.z*x2.x + Wt.w*x3.x;
            float v1 = Wt.x*x0.y + Wt.y*x1.y + Wt.z*x2.y + Wt.w*x3.y;
            float v2 = Wt.x*x0.z + Wt.y*x1.z + Wt.z*x2.z + Wt.w*x3.z;
            float v3 = Wt.x*x0.w + Wt.y*x1.w + Wt.z*x2.w + Wt.w*x3.w;
            a0 = fmaf(wdw_r[k][0], v0, a0);
            a1 = fmaf(wdw_r[k][1], v1, a1);
            a2 = fmaf(wdw_r[k][2], v2, a2);
            a3 = fmaf(wdw_r[k][3], v3, a3);
        }
        int pg = (h0 + (pi >> 4))*Wn + w0 + (pi & 15);
        *(float4*)(midb + (size_t)pg*128) = make_float4(a0, a1, a2, a3);
    }
}

// ---------------------------------------------------------------------------
// K3: pointwise 1x1 as tf32 mma.sync GEMM; B now staged from mid[p][c].
// ---------------------------------------------------------------------------
#define PA 132
#define PC 132
#define K3_SMEM ((128*PA + 128*PC) * 4)

__global__ __launch_bounds__(256) void k3_mma(const float* __restrict__ w_pw,
                                              const float* __restrict__ b_pw,
                                              float* __restrict__ out) {
    extern __shared__ uint32_t smem[];
    uint32_t* sA = smem;             // 128 o x PA  (K-major along c)
    uint32_t* sB = smem + 128*PA;    // 128 px x PC (K-major along c)

    int tid = threadIdx.x;
    int wid = tid >> 5, lid = tid & 31;
    int g = lid >> 2, tig = lid & 3;
    int wm = wid >> 2, wn = wid & 3;

    int o0  = blockIdx.y * 128;
    int p0  = blockIdx.x * 128;      // global pixel base (includes b)
    int b   = p0 / HWn;
    int hw0 = p0 % HWn;

    #pragma unroll
    for (int it = 0; it < 16; it++) {
        int i = it*256 + tid;
        int m = i >> 5, q = i & 31;
        float4 v = *(const float4*)(w_pw + (size_t)(o0 + m)*Cn + q*4);
        uint4 u = { f2tf32(v.x), f2tf32(v.y), f2tf32(v.z), f2tf32(v.w) };
        *(uint4*)(sA + m*PA + q*4) = u;
    }
    const float* midb = g_mid + (size_t)p0*128;
    #pragma unroll
    for (int it = 0; it < 16; it++) {
        int i = it*256 + tid;
        int px = i >> 5, q = i & 31;
        float4 val = *(const float4*)(midb + (size_t)px*128 + q*4);
        uint4 u = { f2tf32(val.x), f2tf32(val.y), f2tf32(val.z), f2tf32(val.w) };
        *(uint4*)(sB + px*PC + q*4) = u;
    }
    __syncthreads();

    float acc[4][4][4];
    #pragma unroll
    for (int mi = 0; mi < 4; mi++)
        #pragma unroll
        for (int ni = 0; ni < 4; ni++)
            #pragma unroll
            for (int j = 0; j < 4; j++) acc[mi][ni][j] = 0.f;

    const uint32_t* sAr = sA + (wm*64 + g)*PA;
    const uint32_t* sBr = sB + (wn*32 + g)*PC;

    #pragma unroll
    for (int ks = 0; ks < 16; ks++) {
        int c0 = ks*8;
        uint32_t a[4][4], bf[4][2];
        #pragma unroll
        for (int mi = 0; mi < 4; mi++) {
            const uint32_t* p = sAr + mi*16*PA + c0 + tig;
            a[mi][0] = p[0];
            a[mi][1] = p[8*PA];
            a[mi][2] = p[4];
            a[mi][3] = p[8*PA + 4];
        }
        #pragma unroll
        for (int ni = 0; ni < 4; ni++) {
            const uint32_t* p = sBr + ni*8*PC + c0 + tig;
            bf[ni][0] = p[0];
            bf[ni][1] = p[4];
        }
        #pragma unroll
        for (int mi = 0; mi < 4; mi++)
            #pragma unroll
            for (int ni = 0; ni < 4; ni++)
                mma_tf32(acc[mi][ni], a[mi][0], a[mi][1], a[mi][2], a[mi][3],
                         bf[ni][0], bf[ni][1]);
    }

    float* outb = out + (size_t)b*On*HWn + hw0 + wn*32;
    #pragma unroll
    for (int mi = 0; mi < 4; mi++) {
        int row = o0 + wm*64 + mi*16 + g;
        float bias0 = b_pw[row];
        float bias1 = b_pw[row + 8];
        float* r0 = outb + (size_t)row*HWn;
        float* r1 = outb + (size_t)(row + 8)*HWn;
        #pragma unroll
        for (int ni = 0; ni < 4; ni++) {
            int col = ni*8 + 2*tig;
            *(float2*)(r0 + col) = make_float2(acc[mi][ni][0] + bias0,
                                               acc[mi][ni][1] + bias0);
            *(float2*)(r1 + col) = make_float2(acc[mi][ni][2] + bias1,
                                               acc[mi][ni][3] + bias1);
        }
    }
}

// ---------------------------------------------------------------------------
extern "C" void kernel_launch(void* const* d_in, const int* in_sizes, int n_in,
                              void* d_out, int out_size) {
    const float* x     = (const float*)d_in[0];
    const float* w_off = (const float*)d_in[1];
    const float* b_off = (const float*)d_in[2];
    const float* w_dw  = (const float*)d_in[3];
    const float* b_dw  = (const float*)d_in[4];
    const float* w_pw  = (const float*)d_in[5];
    const float* b_pw  = (const float*)d_in[6];
    float* out = (float*)d_out;

    cudaFuncSetAttribute(k1_mma, cudaFuncAttributeMaxDynamicSharedMemorySize, K1_SMEM);
    cudaFuncSetAttribute(k3_mma, cudaFuncAttributeMaxDynamicSharedMemorySize, K3_SMEM);

    k0_wk1   <<<(32*1152 + 255)/256, 256>>>(w_off);
    kT       <<<dim3(HWn/32, Cn/32, Bn), 256>>>(x);
    k1_mma   <<<dim3(Hn/2, Bn), 256, K1_SMEM>>>(x);
    k2_sample<<<dim3(Wn/16, Hn/4, Bn), 64>>>(w_dw, b_dw, b_off);
    k3_mma   <<<dim3(Bn*HWn/128, On/128), 256, K3_SMEM>>>(w_pw, b_pw, out);
}